// round 1
// baseline (speedup 1.0000x reference)
#include <cuda_runtime.h>
#include <math.h>
#include <stdint.h>

// LLTM: gates[B,3S] = concat(old_h, input) @ W[K,3S] + bias ; then
// new_h = tanh(old_c + elu(g2)*sig(g0)) * sig(g1), new_cell = old_c + elu(g2)*sig(g0)
// Shapes: B=4096, F=2048, S=2048, K=F+S=4096, N=3S=6144.

#define BM 128
#define BN 128
#define BK 16
#define TM 8
#define TN 8
// threads per CTA = (BM/TM)*(BN/TN) = 256

// Scratch for the gate matrix (B * 3S floats = 96 MB). Device global: allowed.
__device__ float g_gates[4096 * 6144];

__global__ __launch_bounds__(256, 2) void lltm_gemm_kernel(
    const float* __restrict__ W,      // [K, N] row-major
    const float* __restrict__ bias,   // [N]
    const float* __restrict__ input,  // [B, F]
    const float* __restrict__ old_h,  // [B, S]
    int B, int F, int S, int K, int N)
{
    __shared__ float As[BK][BM];      // A stored transposed: As[k][m]
    __shared__ float Bs[BK][BN];      // Bs[k][n]

    const int n0 = blockIdx.x * BN;
    const int m0 = blockIdx.y * BM;

    const int tid = threadIdx.x;
    const int tx = tid % (BN / TN);   // 0..15, column group
    const int ty = tid / (BN / TN);   // 0..15, row group

    float acc[TM][TN];
    #pragma unroll
    for (int i = 0; i < TM; i++)
        #pragma unroll
        for (int j = 0; j < TN; j++)
            acc[i][j] = 0.0f;

    for (int kt = 0; kt < K; kt += BK) {
        // ---- load A tile (gather from concat(old_h, input)), store transposed
        // BM*BK/4 = 512 float4 loads; 2 per thread
        #pragma unroll
        for (int t = tid; t < (BM * BK) / 4; t += 256) {
            int row = t / (BK / 4);          // 0..127 (m within tile)
            int c4  = t % (BK / 4);          // 0..3
            int k   = kt + c4 * 4;
            int gm  = m0 + row;
            const float* src = (k < S)
                ? (old_h + (size_t)gm * S + k)
                : (input + (size_t)gm * F + (k - S));
            float4 v = *(const float4*)src;  // never straddles the S boundary (S%4==0, k%4==0)
            As[c4 * 4 + 0][row] = v.x;
            As[c4 * 4 + 1][row] = v.y;
            As[c4 * 4 + 2][row] = v.z;
            As[c4 * 4 + 3][row] = v.w;
        }
        // ---- load B tile: W rows kt..kt+15, cols n0..n0+127
        #pragma unroll
        for (int t = tid; t < (BK * BN) / 4; t += 256) {
            int row = t / (BN / 4);          // 0..15 (k within tile)
            int c4  = t % (BN / 4);          // 0..31
            float4 v = *(const float4*)(W + (size_t)(kt + row) * N + n0 + c4 * 4);
            *(float4*)&Bs[row][c4 * 4] = v;
        }
        __syncthreads();

        #pragma unroll
        for (int k = 0; k < BK; k++) {
            float regM[TM], regN[TN];
            #pragma unroll
            for (int i = 0; i < TM; i++) regM[i] = As[k][ty * TM + i];
            #pragma unroll
            for (int j = 0; j < TN; j++) regN[j] = Bs[k][tx * TN + j];
            #pragma unroll
            for (int i = 0; i < TM; i++)
                #pragma unroll
                for (int j = 0; j < TN; j++)
                    acc[i][j] = fmaf(regM[i], regN[j], acc[i][j]);
        }
        __syncthreads();
    }

    // ---- write gates (+bias) to scratch
    float bv[TN];
    #pragma unroll
    for (int j = 0; j < TN; j++) bv[j] = bias[n0 + tx * TN + j];

    #pragma unroll
    for (int i = 0; i < TM; i++) {
        int gm = m0 + ty * TM + i;
        float* dst = g_gates + (size_t)gm * N + n0 + tx * TN;
        float4 v0, v1;
        v0.x = acc[i][0] + bv[0]; v0.y = acc[i][1] + bv[1];
        v0.z = acc[i][2] + bv[2]; v0.w = acc[i][3] + bv[3];
        v1.x = acc[i][4] + bv[4]; v1.y = acc[i][5] + bv[5];
        v1.z = acc[i][6] + bv[6]; v1.w = acc[i][7] + bv[7];
        *(float4*)dst = v0;
        *(float4*)(dst + 4) = v1;
    }
}

__global__ __launch_bounds__(256) void lltm_epilogue_kernel(
    const float* __restrict__ old_c,  // [B, S]
    float* __restrict__ out,          // [2, B, S]: new_h then new_cell
    int B, int S)
{
    int i = blockIdx.x * blockDim.x + threadIdx.x;
    int total = B * S;
    if (i >= total) return;
    int b = i / S;
    int s = i - b * S;
    const float* g = g_gates + (size_t)b * (3 * S);

    float g0 = g[s];
    float g1 = g[S + s];
    float g2 = g[2 * S + s];

    float ig = 1.0f / (1.0f + expf(-g0));
    float og = 1.0f / (1.0f + expf(-g1));
    float cand = (g2 > 0.0f) ? g2 : expm1f(g2);
    float nc = old_c[i] + cand * ig;
    float nh = tanhf(nc) * og;

    out[i] = nh;
    out[(size_t)total + i] = nc;
}

extern "C" void kernel_launch(void* const* d_in, const int* in_sizes, int n_in,
                              void* d_out, int out_size) {
    const float* W      = (const float*)d_in[0];  // (F+S, 3S)
    const float* bias   = (const float*)d_in[1];  // (3S,)
    const float* input  = (const float*)d_in[2];  // (B, F)
    const float* old_h  = (const float*)d_in[3];  // (B, S)
    const float* old_c  = (const float*)d_in[4];  // (B, S)
    float* out = (float*)d_out;

    const int S = in_sizes[1] / 3;                // 2048
    const int B = in_sizes[4] / S;                // 4096
    const int F = in_sizes[2] / B;                // 2048
    const int K = F + S;                          // 4096
    const int N = 3 * S;                          // 6144

    dim3 grid(N / BN, B / BM);                    // (48, 32)
    lltm_gemm_kernel<<<grid, 256>>>(W, bias, input, old_h, B, F, S, K, N);

    int total = B * S;
    lltm_epilogue_kernel<<<(total + 255) / 256, 256>>>(old_c, out, B, S);
}

// round 4
// speedup vs baseline: 2.1591x; 2.1591x over previous
#include <cuda_runtime.h>
#include <cuda_fp16.h>
#include <math.h>
#include <stdint.h>

// LLTM on GB300 via compute_103-baseline PTX (no tcgen05 available in this build):
// gates = concat(old_h, input) @ W + bias, fused activations.
// GEMM: fp16x3 split emulation of fp32 (h1*w1 + h1*w2 + h2*w1), fp32 accum,
// Ampere-style mma.sync.m16n8k16 + ldmatrix + cp.async 4-stage pipeline.
// W pre-transposed to Wt[n][k]. CTA tile 128m x 96n, n gate-planar
// (rows 0-31: gate0 s-chunk, 32-63: gate1, 64-95: gate2) -> register-fused epilogue.
// Shapes: B=4096, F=2048, S=2048, K=4096, N=6144.

#define S_DIM 2048
#define B_DIM 4096
#define K_DIM 4096
#define N_DIM 6144
#define BK    32
#define NITER (K_DIM / BK)     // 128
#define STAGES 4

// smem geometry: fp16 tiles, row = 32 halves, padded stride 80 bytes.
#define RSB      80
#define OFF_AH   0
#define OFF_AL   10240          // 128*80
#define OFF_BH   20480
#define OFF_BL   28160          // +96*80
#define STAGE_SZ 35840
#define SMEM_TOTAL (STAGES * STAGE_SZ)   // 143360

// ---------------- device scratch ----------------
__device__ __half g_Wh1[(size_t)N_DIM * K_DIM];
__device__ __half g_Wl2[(size_t)N_DIM * K_DIM];
__device__ __half g_Xh1[(size_t)B_DIM * K_DIM];
__device__ __half g_Xl2[(size_t)B_DIM * K_DIM];

// ---------------- helpers ----------------
__device__ __forceinline__ uint32_t smem_u32(const void* p) {
    uint32_t a;
    asm("{ .reg .u64 t; cvta.to.shared.u64 t, %1; cvt.u32.u64 %0, t; }" : "=r"(a) : "l"(p));
    return a;
}
__device__ __forceinline__ void cp_async16(uint32_t sdst, const void* gsrc) {
    asm volatile("cp.async.cg.shared.global [%0], [%1], 16;" :: "r"(sdst), "l"(gsrc) : "memory");
}
__device__ __forceinline__ void cp_commit() {
    asm volatile("cp.async.commit_group;" ::: "memory");
}
__device__ __forceinline__ void cp_wait2() {
    asm volatile("cp.async.wait_group 2;" ::: "memory");
}
__device__ __forceinline__ void ldsm_x4(uint32_t& r0, uint32_t& r1, uint32_t& r2, uint32_t& r3,
                                        uint32_t addr) {
    asm volatile("ldmatrix.sync.aligned.m8n8.x4.shared.b16 {%0,%1,%2,%3}, [%4];"
                 : "=r"(r0), "=r"(r1), "=r"(r2), "=r"(r3) : "r"(addr));
}
__device__ __forceinline__ void mma16816(float* c, const uint32_t* a, uint32_t b0, uint32_t b1) {
    asm volatile("mma.sync.aligned.m16n8k16.row.col.f32.f16.f16.f32 "
                 "{%0,%1,%2,%3}, {%4,%5,%6,%7}, {%8,%9}, {%0,%1,%2,%3};"
                 : "+f"(c[0]), "+f"(c[1]), "+f"(c[2]), "+f"(c[3])
                 : "r"(a[0]), "r"(a[1]), "r"(a[2]), "r"(a[3]), "r"(b0), "r"(b1));
}

// ---------------- pre-pass: split X = concat(old_h, input) into fp16 hi/lo ----------------
__global__ __launch_bounds__(256) void split_x_kernel(const float* __restrict__ input,
                                                      const float* __restrict__ old_h) {
    size_t idx = ((size_t)blockIdx.x * blockDim.x + threadIdx.x) * 4;
    int b = (int)(idx / K_DIM);
    int k = (int)(idx % K_DIM);
    const float* src = (k < S_DIM) ? old_h + (size_t)b * S_DIM + k
                                   : input + (size_t)b * (K_DIM - S_DIM) + (k - S_DIM);
    float4 v = *(const float4*)src;
    float vv[4] = {v.x, v.y, v.z, v.w};
    union { __half h[4]; uint2 u; } hi, lo;
    #pragma unroll
    for (int e = 0; e < 4; e++) {
        hi.h[e] = __float2half_rn(vv[e]);
        lo.h[e] = __float2half_rn(vv[e] - __half2float(hi.h[e]));
    }
    *(uint2*)&g_Xh1[idx] = hi.u;
    *(uint2*)&g_Xl2[idx] = lo.u;
}

// ---------------- pre-pass: transpose W[K,N] -> Wt[N,K] fp16 hi/lo ----------------
__global__ __launch_bounds__(256) void split_w_kernel(const float* __restrict__ W) {
    __shared__ float sh[32][33];
    int n0 = blockIdx.x * 32;
    int k0 = blockIdx.y * 32;
    int tx = threadIdx.x, ty = threadIdx.y;
    #pragma unroll
    for (int i = 0; i < 4; i++) {
        int k = k0 + ty + i * 8;
        sh[ty + i * 8][tx] = W[(size_t)k * N_DIM + n0 + tx];
    }
    __syncthreads();
    #pragma unroll
    for (int i = 0; i < 4; i++) {
        int nl = ty + i * 8;
        float v = sh[tx][nl];
        __half hi = __float2half_rn(v);
        __half lo = __float2half_rn(v - __half2float(hi));
        size_t off = (size_t)(n0 + nl) * K_DIM + k0 + tx;
        g_Wh1[off] = hi;
        g_Wl2[off] = lo;
    }
}

// ---------------- main fused GEMM + LLTM ----------------
__global__ __launch_bounds__(256, 1) void lltm_mma_kernel(
    const float* __restrict__ bias,
    const float* __restrict__ old_c,
    float* __restrict__ out)
{
    extern __shared__ char smem[];
    const uint32_t sb = smem_u32(smem);

    const int tid  = threadIdx.x;
    const int wid  = tid >> 5;
    const int lane = tid & 31;
    const int m0 = blockIdx.x * 128;
    const int s0 = blockIdx.y * 32;

    // ---- per-thread cp.async chunk plan: 1792 16B chunks / 256 threads = 7 each
    uint32_t sm_off[7];
    const char* gp[7];
    #pragma unroll
    for (int i = 0; i < 7; i++) {
        int c = tid + i * 256;
        if (c < 1024) {
            int mat = c >> 9;            // 0: Xh1, 1: Xl2
            int idx = c & 511;
            int r = idx >> 2, c16 = idx & 3;
            sm_off[i] = (mat ? OFF_AL : OFF_AH) + r * RSB + c16 * 16;
            const __half* base = mat ? g_Xl2 : g_Xh1;
            gp[i] = (const char*)(base + (size_t)(m0 + r) * K_DIM + c16 * 8);
        } else {
            int cc = c - 1024;
            int mat = cc / 384;          // 0: Wh1, 1: Wl2
            int idx = cc % 384;
            int r = idx >> 2, c16 = idx & 3;
            int n = (r >> 5) * S_DIM + s0 + (r & 31);   // gate-planar row
            sm_off[i] = (mat ? OFF_BL : OFF_BH) + r * RSB + c16 * 16;
            const __half* base = mat ? g_Wl2 : g_Wh1;
            gp[i] = (const char*)(base + (size_t)n * K_DIM + c16 * 8);
        }
    }

    // ---- ldmatrix lane offset (same pattern for A and B tiles)
    const uint32_t laneOff = (uint32_t)(((lane & 7) + ((lane >> 3) & 1) * 8) * RSB
                                        + (lane >> 4) * 16);
    const uint32_t aBase = sb + wid * (16 * RSB) + laneOff;   // + stage + OFF_AH/AL + kk*32
    const uint32_t bBase = sb + laneOff;                      // + stage + OFF_BH/BL + t*1280 + kk*32

    float acc[12][4];
    #pragma unroll
    for (int j = 0; j < 12; j++)
        #pragma unroll
        for (int e = 0; e < 4; e++) acc[j][e] = 0.0f;

    // ---- prologue: fill STAGES-1 stages
    #pragma unroll
    for (int st = 0; st < STAGES - 1; st++) {
        #pragma unroll
        for (int i = 0; i < 7; i++)
            cp_async16(sb + st * STAGE_SZ + sm_off[i], gp[i] + (size_t)st * (BK * 2));
        cp_commit();
    }

    int rd = 0, wr = STAGES - 1;
    for (int kt = 0; kt < NITER; kt++) {
        cp_wait2();
        __syncthreads();

        if (kt + STAGES - 1 < NITER) {
            #pragma unroll
            for (int i = 0; i < 7; i++)
                cp_async16(sb + wr * STAGE_SZ + sm_off[i],
                           gp[i] + (size_t)(kt + STAGES - 1) * (BK * 2));
        }
        cp_commit();

        const uint32_t stg = (uint32_t)(rd * STAGE_SZ);
        #pragma unroll
        for (int kk = 0; kk < 2; kk++) {
            const uint32_t ko = kk * 32;
            uint32_t ah[4], al[4], bf[6][4];
            ldsm_x4(ah[0], ah[1], ah[2], ah[3], aBase + stg + OFF_AH + ko);
            ldsm_x4(al[0], al[1], al[2], al[3], aBase + stg + OFF_AL + ko);
            #pragma unroll
            for (int t = 0; t < 6; t++)
                ldsm_x4(bf[t][0], bf[t][1], bf[t][2], bf[t][3],
                        bBase + stg + OFF_BH + t * (16 * RSB) + ko);
            #pragma unroll
            for (int t = 0; t < 6; t++) {
                mma16816(acc[2 * t],     ah, bf[t][0], bf[t][2]);
                mma16816(acc[2 * t + 1], ah, bf[t][1], bf[t][3]);
            }
            #pragma unroll
            for (int t = 0; t < 6; t++) {
                mma16816(acc[2 * t],     al, bf[t][0], bf[t][2]);
                mma16816(acc[2 * t + 1], al, bf[t][1], bf[t][3]);
            }
            #pragma unroll
            for (int t = 0; t < 6; t++) {
                ldsm_x4(bf[t][0], bf[t][1], bf[t][2], bf[t][3],
                        bBase + stg + OFF_BL + t * (16 * RSB) + ko);
                mma16816(acc[2 * t],     ah, bf[t][0], bf[t][2]);
                mma16816(acc[2 * t + 1], ah, bf[t][1], bf[t][3]);
            }
        }
        rd = (rd + 1) & (STAGES - 1);
        wr = (wr + 1) & (STAGES - 1);
    }

    // ---- register-fused LLTM epilogue
    // acc tile j covers n-rows [8j, 8j+8): gate = j/4, s_loc = 8*(j%4) + col.
    // Thread holds cols (lane%4)*2 + {0,1}, rows lane/4 and lane/4+8.
    const int row0 = m0 + wid * 16 + (lane >> 2);
    const int scol = (lane & 3) * 2;
    const size_t BS = (size_t)B_DIM * S_DIM;

    #pragma unroll
    for (int j = 0; j < 4; j++) {
        const int sg = s0 + 8 * j + scol;           // global s of element e=0
        const float b0a = __ldg(bias + sg);
        const float b0b = __ldg(bias + sg + 1);
        const float b1a = __ldg(bias + S_DIM + sg);
        const float b1b = __ldg(bias + S_DIM + sg + 1);
        const float b2a = __ldg(bias + 2 * S_DIM + sg);
        const float b2b = __ldg(bias + 2 * S_DIM + sg + 1);
        #pragma unroll
        for (int h = 0; h < 2; h++) {
            const int m = row0 + 8 * h;
            const size_t o = (size_t)m * S_DIM + sg;
            const float2 oc = *(const float2*)(old_c + o);
            float nh[2], nc[2];
            #pragma unroll
            for (int e = 0; e < 2; e++) {
                float g0 = acc[j][2 * h + e]     + (e ? b0b : b0a);
                float g1 = acc[j + 4][2 * h + e] + (e ? b1b : b1a);
                float g2 = acc[j + 8][2 * h + e] + (e ? b2b : b2a);
                float ig = 1.0f / (1.0f + __expf(-g0));
                float og = 1.0f / (1.0f + __expf(-g1));
                float cand = (g2 > 0.0f) ? g2 : expm1f(g2);
                float ncv = (e ? oc.y : oc.x) + cand * ig;
                nc[e] = ncv;
                nh[e] = tanhf(ncv) * og;
            }
            *(float2*)(out + o) = make_float2(nh[0], nh[1]);
            *(float2*)(out + BS + o) = make_float2(nc[0], nc[1]);
        }
    }
}

// ---------------- launch ----------------
extern "C" void kernel_launch(void* const* d_in, const int* in_sizes, int n_in,
                              void* d_out, int out_size) {
    const float* W     = (const float*)d_in[0];
    const float* bias  = (const float*)d_in[1];
    const float* input = (const float*)d_in[2];
    const float* old_h = (const float*)d_in[3];
    const float* old_c = (const float*)d_in[4];
    float* out = (float*)d_out;

    cudaFuncSetAttribute(lltm_mma_kernel, cudaFuncAttributeMaxDynamicSharedMemorySize, SMEM_TOTAL);

    {
        size_t nthreads = (size_t)B_DIM * K_DIM / 4;
        split_x_kernel<<<(int)(nthreads / 256), 256>>>(input, old_h);
        dim3 g(N_DIM / 32, K_DIM / 32);
        split_w_kernel<<<g, dim3(32, 8)>>>(W);
    }

    dim3 grid(B_DIM / 128, S_DIM / 32);    // (32, 64)
    lltm_mma_kernel<<<grid, 256, SMEM_TOTAL>>>(bias, old_c, out);
}